// round 1
// baseline (speedup 1.0000x reference)
#include <cuda_runtime.h>
#include <cstdint>

#define H_    56
#define W_    56
#define NH_   12
#define HD    64
#define NTOK  3137          // 56*56 + 1
#define C_    768
#define C3    2304
#define B_    8
#define MTOT  (B_ * NTOK)   // 25096

// Scratch (no cudaMalloc allowed): QKV activations + attention output
__device__ float g_qkv[(size_t)B_ * NTOK * C3];   // 57,815,040 floats
__device__ float g_att[(size_t)B_ * NTOK * C_];   // 19,271,680 floats

// ---------------------------------------------------------------------------
// Tiled SGEMM: C[M,N] = A[M,K] @ B[K,N] (+ bias). Row-major. N%128==0, K%8==0.
// 128x128 tile, 8x8 per thread, 256 threads.
// ---------------------------------------------------------------------------
__global__ __launch_bounds__(256) void sgemm_kernel(
    const float* __restrict__ A, const float* __restrict__ B,
    float* __restrict__ C, const float* __restrict__ bias,
    int M, int N, int K)
{
    __shared__ float As[8][128];
    __shared__ float Bs[8][128];

    const int tid  = threadIdx.x;
    const int row0 = blockIdx.y * 128;
    const int col0 = blockIdx.x * 128;

    const int arow = tid >> 1;           // 0..127
    const int acol = (tid & 1) * 4;      // 0 or 4
    const int brow = tid >> 5;           // 0..7
    const int bcol = (tid & 31) * 4;     // 0..124

    const int ty = tid >> 4;             // 0..15
    const int tx = tid & 15;             // 0..15

    float acc[8][8];
#pragma unroll
    for (int i = 0; i < 8; ++i)
#pragma unroll
        for (int j = 0; j < 8; ++j) acc[i][j] = 0.f;

    const bool arow_ok = (row0 + arow) < M;
    const float* Aptr = A + (size_t)(row0 + arow) * K + acol;
    const float* Bptr = B + (size_t)brow * N + col0 + bcol;

    for (int k0 = 0; k0 < K; k0 += 8) {
        float4 av = arow_ok ? *(const float4*)(Aptr + k0)
                            : make_float4(0.f, 0.f, 0.f, 0.f);
        float4 bv = *(const float4*)(Bptr + (size_t)k0 * N);
        As[acol + 0][arow] = av.x;
        As[acol + 1][arow] = av.y;
        As[acol + 2][arow] = av.z;
        As[acol + 3][arow] = av.w;
        *(float4*)&Bs[brow][bcol] = bv;
        __syncthreads();

#pragma unroll
        for (int kk = 0; kk < 8; ++kk) {
            float af[8], bf[8];
#pragma unroll
            for (int i = 0; i < 8; ++i) af[i] = As[kk][ty * 8 + i];
#pragma unroll
            for (int j = 0; j < 8; ++j) bf[j] = Bs[kk][tx * 8 + j];
#pragma unroll
            for (int i = 0; i < 8; ++i)
#pragma unroll
                for (int j = 0; j < 8; ++j) acc[i][j] += af[i] * bf[j];
        }
        __syncthreads();
    }

#pragma unroll
    for (int i = 0; i < 8; ++i) {
        int gr = row0 + ty * 8 + i;
        if (gr < M) {
            float* cp = C + (size_t)gr * N + col0 + tx * 8;
#pragma unroll
            for (int j = 0; j < 8; ++j) {
                float v = acc[i][j];
                if (bias) v += bias[col0 + tx * 8 + j];
                cp[j] = v;
            }
        }
    }
}

// ---------------------------------------------------------------------------
// Spatial criss-cross attention. One block per (b,h,w); one warp per head.
// Combined softmax over [cls, 56 column keys, 56 row keys(self masked)] = 113.
// ---------------------------------------------------------------------------
__global__ __launch_bounds__(384) void attn_spatial(
    const float* __restrict__ qkv, float* __restrict__ out)
{
    const int blk  = blockIdx.x;         // b*H*W + h*W + w
    const int w    = blk % W_;
    const int h    = (blk / W_) % H_;
    const int b    = blk / (W_ * H_);
    const int warp = threadIdx.x >> 5;   // head
    const int lane = threadIdx.x & 31;

    __shared__ float sc[NH_][128];       // 113 scores per head (padded)

    const float* base = qkv + (size_t)b * NTOK * C3;
    const int    nq   = 1 + h * W_ + w;
    const float* qp   = base + (size_t)nq * C3 + warp * HD;
    const float  qa   = qp[lane];
    const float  qb   = qp[lane + 32];

    // column keys: idx 0 = cls, idx kk -> grid row kk-1 of column w (includes self)
    for (int kk = 0; kk < 57; ++kk) {
        int n = (kk == 0) ? 0 : (1 + (kk - 1) * W_ + w);
        const float* kp = base + (size_t)n * C3 + C_ + warp * HD;
        float p = qa * kp[lane] + qb * kp[lane + 32];
#pragma unroll
        for (int o = 16; o; o >>= 1) p += __shfl_xor_sync(~0u, p, o);
        if (lane == 0) sc[warp][kk] = p * 0.125f;
    }
    // row keys: column kk of row h; self (kk==w) masked
    for (int kk = 0; kk < 56; ++kk) {
        int n = 1 + h * W_ + kk;
        const float* kp = base + (size_t)n * C3 + C_ + warp * HD;
        float p = qa * kp[lane] + qb * kp[lane + 32];
#pragma unroll
        for (int o = 16; o; o >>= 1) p += __shfl_xor_sync(~0u, p, o);
        if (lane == 0) sc[warp][57 + kk] = (kk == w) ? -1e30f : p * 0.125f;
    }
    __syncwarp();

    // softmax over 113
    float m = -1e30f;
    for (int i = lane; i < 113; i += 32) m = fmaxf(m, sc[warp][i]);
#pragma unroll
    for (int o = 16; o; o >>= 1) m = fmaxf(m, __shfl_xor_sync(~0u, m, o));
    float s = 0.f;
    for (int i = lane; i < 113; i += 32) {
        float e = __expf(sc[warp][i] - m);
        sc[warp][i] = e;
        s += e;
    }
#pragma unroll
    for (int o = 16; o; o >>= 1) s += __shfl_xor_sync(~0u, s, o);
    __syncwarp();
    const float inv = 1.f / s;

    // weighted sum of V over the same 113 keys
    float oa = 0.f, ob = 0.f;
    for (int kk = 0; kk < 57; ++kk) {
        int n = (kk == 0) ? 0 : (1 + (kk - 1) * W_ + w);
        const float* vp = base + (size_t)n * C3 + 2 * C_ + warp * HD;
        float p = sc[warp][kk];
        oa += p * vp[lane];
        ob += p * vp[lane + 32];
    }
    for (int kk = 0; kk < 56; ++kk) {
        int n = 1 + h * W_ + kk;
        const float* vp = base + (size_t)n * C3 + 2 * C_ + warp * HD;
        float p = sc[warp][57 + kk];
        oa += p * vp[lane];
        ob += p * vp[lane + 32];
    }

    float* op = out + ((size_t)b * NTOK + nq) * C_ + warp * HD;
    op[lane]      = oa * inv;
    op[lane + 32] = ob * inv;
}

// ---------------------------------------------------------------------------
// CLS-token attention: one block per (b, head), softmax over all 3137 keys.
// ---------------------------------------------------------------------------
__global__ __launch_bounds__(256) void attn_cls(
    const float* __restrict__ qkv, float* __restrict__ out)
{
    const int b  = blockIdx.x / NH_;
    const int nh = blockIdx.x % NH_;
    const int tid = threadIdx.x;

    __shared__ float qs[HD];
    __shared__ float sc[NTOK];
    __shared__ float red[256];
    __shared__ float part[4][HD];

    const float* base = qkv + (size_t)b * NTOK * C3;
    if (tid < HD) qs[tid] = base[nh * HD + tid];
    __syncthreads();

    for (int n = tid; n < NTOK; n += 256) {
        const float* kp = base + (size_t)n * C3 + C_ + nh * HD;
        float s = 0.f;
#pragma unroll
        for (int d = 0; d < HD; ++d) s += qs[d] * kp[d];
        sc[n] = s * 0.125f;
    }
    __syncthreads();

    // block max
    float m = -1e30f;
    for (int n = tid; n < NTOK; n += 256) m = fmaxf(m, sc[n]);
    red[tid] = m;
    __syncthreads();
    for (int st = 128; st; st >>= 1) {
        if (tid < st) red[tid] = fmaxf(red[tid], red[tid + st]);
        __syncthreads();
    }
    m = red[0];
    __syncthreads();

    // exp + block sum
    float s = 0.f;
    for (int n = tid; n < NTOK; n += 256) {
        float e = __expf(sc[n] - m);
        sc[n] = e;
        s += e;
    }
    red[tid] = s;
    __syncthreads();
    for (int st = 128; st; st >>= 1) {
        if (tid < st) red[tid] += red[tid + st];
        __syncthreads();
    }
    const float inv = 1.f / red[0];
    __syncthreads();

    // weighted V sum: thread -> (dim, key-chunk)
    const int d = tid & 63, chunk = tid >> 6;
    float acc = 0.f;
    for (int n = chunk; n < NTOK; n += 4) {
        const float* vp = base + (size_t)n * C3 + 2 * C_ + nh * HD;
        acc += sc[n] * vp[d];
    }
    part[chunk][d] = acc;
    __syncthreads();
    if (chunk == 0) {
        float r = (part[0][d] + part[1][d] + part[2][d] + part[3][d]) * inv;
        out[(size_t)b * NTOK * C_ + nh * HD + d] = r;
    }
}

// ---------------------------------------------------------------------------
extern "C" void kernel_launch(void* const* d_in, const int* in_sizes, int n_in,
                              void* d_out, int out_size)
{
    const float* x     = (const float*)d_in[0];   // (8, 3137, 768)
    const float* Wqkv  = (const float*)d_in[1];   // (768, 2304)
    const float* Wproj = (const float*)d_in[2];   // (768, 768)
    const float* bproj = (const float*)d_in[3];   // (768,)
    float* out = (float*)d_out;                   // (8, 3137, 768)

    float *qkv = nullptr, *att = nullptr;
    cudaGetSymbolAddress((void**)&qkv, g_qkv);
    cudaGetSymbolAddress((void**)&att, g_att);

    // 1) QKV projection: (25096,768) @ (768,2304)
    {
        dim3 grid(C3 / 128, (MTOT + 127) / 128);
        sgemm_kernel<<<grid, 256>>>(x, Wqkv, qkv, nullptr, MTOT, C3, C_);
    }
    // 2) spatial criss-cross attention
    attn_spatial<<<B_ * H_ * W_, 384>>>(qkv, att);
    // 3) cls attention
    attn_cls<<<B_ * NH_, 256>>>(qkv, att);
    // 4) output projection + bias: (25096,768) @ (768,768)
    {
        dim3 grid(C_ / 128, (MTOT + 127) / 128);
        sgemm_kernel<<<grid, 256>>>(att, Wproj, out, bproj, MTOT, C_, C_);
    }
}